// round 2
// baseline (speedup 1.0000x reference)
#include <cuda_runtime.h>
#include <cstdint>

#define BATCH 16384
#define DIM   1024
#define NLAY  6
#define NMC   64
#define HW    16

#define BM 128
#define BN 128
#define BK 16

// ---------------- scratch (static device globals; no cudaMalloc allowed) ----------------
__device__ float g_Wei[NLAY * DIM * 2 * DIM];     // fused [l][k][n], n<1024: We cols, else Wi cols (48MB)
__device__ float g_bei[NLAY * 2 * DIM];           // fused bias [l][be | bi]
__device__ float g_excinh[(size_t)BATCH * 2 * DIM]; // [B, 2048] exc|inh          (128MB)
__device__ float g_mc[(size_t)BATCH * DIM];         // [B, 1024]                   (64MB)
__device__ float g_lat[(size_t)BATCH * DIM];        // [B, 1024]                   (64MB)

// ---------------- weight / bias repack ----------------
// We,Wi: [L, NMC, D, H].  Packed: g_Wei[l][k][n], n=m*H+h -> We[l,m,k,h] (n<D) or Wi (n>=D)
__global__ void pack_wei_kernel(const float* __restrict__ We, const float* __restrict__ Wi) {
    size_t i = (size_t)blockIdx.x * blockDim.x + threadIdx.x;
    const size_t total = (size_t)NLAY * DIM * 2 * DIM;
    if (i >= total) return;
    int l = (int)(i / ((size_t)DIM * 2 * DIM));
    size_t r = i % ((size_t)DIM * 2 * DIM);
    int k = (int)(r / (2 * DIM));
    int n = (int)(r % (2 * DIM));
    const float* src;
    int nn;
    if (n < DIM) { src = We; nn = n; } else { src = Wi; nn = n - DIM; }
    int m = nn / HW, h = nn % HW;
    g_Wei[i] = src[(((size_t)l * NMC + m) * DIM + k) * HW + h];
}

__global__ void pack_bias_kernel(const float* __restrict__ be, const float* __restrict__ bi) {
    int i = blockIdx.x * blockDim.x + threadIdx.x;
    if (i >= NLAY * 2 * DIM) return;
    int l = i / (2 * DIM);
    int n = i % (2 * DIM);
    g_bei[i] = (n < DIM) ? be[l * DIM + n] : bi[l * DIM + (n - DIM)];
}

// ---------------- fp32 SGEMM: C = epi(A[M,K] @ W[K,N] + bias) ----------------
// EPI 0: bias            EPI 1: bias + relu            EPI 2: C += A@W + bias
template <int EPI>
__global__ __launch_bounds__(256, 2)
void sgemm_kernel(const float* __restrict__ A, const float* __restrict__ W,
                  const float* __restrict__ bias, float* __restrict__ C, int N) {
    const int K = DIM;  // 1024
    __shared__ float As[2][BK][BM];
    __shared__ float Bs[2][BK][BN];

    const int tid = threadIdx.x;
    const int bx = blockIdx.x;   // N tile
    const int by = blockIdx.y;   // M tile

    const float* Ab = A + (size_t)by * BM * K;
    const float* Wb = W + (size_t)bx * BN;

    // global-load mapping: A tile 128x16 (512 float4), B tile 16x128 (512 float4); 2 each/thread
    const int arow = tid >> 2;            // 0..63
    const int acol = (tid & 3) << 2;      // 0,4,8,12
    const int brow = tid >> 5;            // 0..7
    const int bcol = (tid & 31) << 2;     // 0..124

    const int tx = tid & 15;
    const int ty = tid >> 4;

    float acc[8][8];
#pragma unroll
    for (int i = 0; i < 8; i++)
#pragma unroll
        for (int j = 0; j < 8; j++) acc[i][j] = 0.f;

    float4 pa0, pa1, pb0, pb1;

    // prologue: tile 0
    pa0 = *(const float4*)(Ab + (size_t)arow * K + acol);
    pa1 = *(const float4*)(Ab + (size_t)(arow + 64) * K + acol);
    pb0 = *(const float4*)(Wb + (size_t)brow * N + bcol);
    pb1 = *(const float4*)(Wb + (size_t)(brow + 8) * N + bcol);
    As[0][acol + 0][arow] = pa0.x; As[0][acol + 1][arow] = pa0.y;
    As[0][acol + 2][arow] = pa0.z; As[0][acol + 3][arow] = pa0.w;
    As[0][acol + 0][arow + 64] = pa1.x; As[0][acol + 1][arow + 64] = pa1.y;
    As[0][acol + 2][arow + 64] = pa1.z; As[0][acol + 3][arow + 64] = pa1.w;
    *(float4*)&Bs[0][brow][bcol] = pb0;
    *(float4*)&Bs[0][brow + 8][bcol] = pb1;
    __syncthreads();

    const int NT = K / BK;  // 64
    for (int t = 0; t < NT; t++) {
        const int cur = t & 1;
        if (t + 1 < NT) {
            const int ko = (t + 1) * BK;
            pa0 = *(const float4*)(Ab + (size_t)arow * K + ko + acol);
            pa1 = *(const float4*)(Ab + (size_t)(arow + 64) * K + ko + acol);
            pb0 = *(const float4*)(Wb + (size_t)(ko + brow) * N + bcol);
            pb1 = *(const float4*)(Wb + (size_t)(ko + brow + 8) * N + bcol);
        }
#pragma unroll
        for (int k = 0; k < BK; k++) {
            float ar[8], br[8];
            *(float4*)&ar[0] = *(const float4*)&As[cur][k][ty * 4];
            *(float4*)&ar[4] = *(const float4*)&As[cur][k][ty * 4 + 64];
            *(float4*)&br[0] = *(const float4*)&Bs[cur][k][tx * 4];
            *(float4*)&br[4] = *(const float4*)&Bs[cur][k][tx * 4 + 64];
#pragma unroll
            for (int i = 0; i < 8; i++)
#pragma unroll
                for (int j = 0; j < 8; j++) acc[i][j] += ar[i] * br[j];
        }
        if (t + 1 < NT) {
            const int nxt = cur ^ 1;
            As[nxt][acol + 0][arow] = pa0.x; As[nxt][acol + 1][arow] = pa0.y;
            As[nxt][acol + 2][arow] = pa0.z; As[nxt][acol + 3][arow] = pa0.w;
            As[nxt][acol + 0][arow + 64] = pa1.x; As[nxt][acol + 1][arow + 64] = pa1.y;
            As[nxt][acol + 2][arow + 64] = pa1.z; As[nxt][acol + 3][arow + 64] = pa1.w;
            *(float4*)&Bs[nxt][brow][bcol] = pb0;
            *(float4*)&Bs[nxt][brow + 8][bcol] = pb1;
            __syncthreads();
        }
    }

    // epilogue
    const int row0 = by * BM + ty * 4;
    const int col0 = bx * BN + tx * 4;
#pragma unroll
    for (int ii = 0; ii < 2; ii++) {
#pragma unroll
        for (int i = 0; i < 4; i++) {
            const int r = row0 + ii * 64 + i;
            float* Crow = C + (size_t)r * N;
#pragma unroll
            for (int jj = 0; jj < 2; jj++) {
                const int c = col0 + jj * 64;
                float4 bv = *(const float4*)(bias + c);
                float4 v;
                v.x = acc[ii * 4 + i][jj * 4 + 0] + bv.x;
                v.y = acc[ii * 4 + i][jj * 4 + 1] + bv.y;
                v.z = acc[ii * 4 + i][jj * 4 + 2] + bv.z;
                v.w = acc[ii * 4 + i][jj * 4 + 3] + bv.w;
                if (EPI == 1) {
                    v.x = fmaxf(v.x, 0.f); v.y = fmaxf(v.y, 0.f);
                    v.z = fmaxf(v.z, 0.f); v.w = fmaxf(v.w, 0.f);
                } else if (EPI == 2) {
                    float4 old = *(const float4*)(Crow + c);
                    v.x += old.x; v.y += old.y; v.z += old.z; v.w += old.w;
                }
                *(float4*)(Crow + c) = v;
            }
        }
    }
}

// ---------------- minicolumn block-diag: mc = relu(exc - (inh @ Wl[m] + bl[m])) ----------------
// excinh: [B, 2048]  (exc cols 0..1023, inh cols 1024..2047)
// Wl: layer slice [NMC][H][H], bl: [NMC][H]
__global__ __launch_bounds__(256)
void mc_kernel(const float* __restrict__ excinh, const float* __restrict__ Wl,
               const float* __restrict__ bl, float* __restrict__ mc) {
    __shared__ float sW[HW * HW];
    __shared__ float sb[HW];
    const int m = blockIdx.y;
    if (threadIdx.x < HW * HW) sW[threadIdx.x] = Wl[m * HW * HW + threadIdx.x];
    if (threadIdx.x < HW)      sb[threadIdx.x] = bl[m * HW + threadIdx.x];
    __syncthreads();

    const int b = blockIdx.x * 256 + threadIdx.x;
    const float* row = excinh + (size_t)b * (2 * DIM);

    float inh[HW], exc[HW];
#pragma unroll
    for (int j = 0; j < 4; j++) {
        float4 vi = *(const float4*)(row + DIM + m * HW + j * 4);
        inh[j * 4 + 0] = vi.x; inh[j * 4 + 1] = vi.y; inh[j * 4 + 2] = vi.z; inh[j * 4 + 3] = vi.w;
        float4 ve = *(const float4*)(row + m * HW + j * 4);
        exc[j * 4 + 0] = ve.x; exc[j * 4 + 1] = ve.y; exc[j * 4 + 2] = ve.z; exc[j * 4 + 3] = ve.w;
    }

    float out[HW];
#pragma unroll
    for (int k = 0; k < HW; k++) {
        float lat = sb[k];
#pragma unroll
        for (int h = 0; h < HW; h++) lat += inh[h] * sW[h * HW + k];
        out[k] = fmaxf(exc[k] - lat, 0.f);
    }

    float* dst = mc + (size_t)b * DIM + m * HW;
#pragma unroll
    for (int j = 0; j < 4; j++) {
        float4 v;
        v.x = out[j * 4 + 0]; v.y = out[j * 4 + 1]; v.z = out[j * 4 + 2]; v.w = out[j * 4 + 3];
        *(float4*)(dst + j * 4) = v;
    }
}

// ---------------- driver ----------------
extern "C" void kernel_launch(void* const* d_in, const int* in_sizes, int n_in,
                              void* d_out, int out_size) {
    const float* x    = (const float*)d_in[0];
    const float* We   = (const float*)d_in[1];
    const float* be   = (const float*)d_in[2];
    const float* Wi   = (const float*)d_in[3];
    const float* bi   = (const float*)d_in[4];
    const float* Wl   = (const float*)d_in[5];
    const float* bl   = (const float*)d_in[6];
    const float* Wlat = (const float*)d_in[7];
    const float* blat = (const float*)d_in[8];
    const float* Wv   = (const float*)d_in[9];
    const float* bv   = (const float*)d_in[10];
    const float* Wo   = (const float*)d_in[11];
    const float* bo   = (const float*)d_in[12];
    const float* fbW  = (const float*)d_in[13];
    const float* fbb  = (const float*)d_in[14];
    float* out = (float*)d_out;

    const size_t BD = (size_t)BATCH * DIM;
    const size_t DD = (size_t)DIM * DIM;

    float* g_Wei_p;     cudaGetSymbolAddress((void**)&g_Wei_p, g_Wei);
    float* g_bei_p;     cudaGetSymbolAddress((void**)&g_bei_p, g_bei);
    float* g_excinh_p;  cudaGetSymbolAddress((void**)&g_excinh_p, g_excinh);
    float* g_mc_p;      cudaGetSymbolAddress((void**)&g_mc_p, g_mc);
    float* g_lat_p;     cudaGetSymbolAddress((void**)&g_lat_p, g_lat);

    // repack fused We|Wi weights + biases (every call: deterministic, ~15us)
    {
        size_t total = (size_t)NLAY * DIM * 2 * DIM;
        pack_wei_kernel<<<(unsigned)((total + 255) / 256), 256>>>(We, Wi);
        pack_bias_kernel<<<(NLAY * 2 * DIM + 255) / 256, 256>>>(be, bi);
    }

    dim3 blk(256);
    dim3 grid_wide(2 * DIM / BN, BATCH / BM);  // N = 2048
    dim3 grid_sq(DIM / BN, BATCH / BM);        // N = 1024
    dim3 grid_mc(BATCH / 256, NMC);

    for (int l = 0; l < NLAY; l++) {
        const float* xin = (l == 0) ? x : (out + (size_t)(l - 1) * BD);
        // exc|inh = relu(x @ Wei + bei)
        sgemm_kernel<1><<<grid_wide, blk>>>(xin, g_Wei_p + (size_t)l * DIM * 2 * DIM,
                                            g_bei_p + (size_t)l * 2 * DIM, g_excinh_p, 2 * DIM);
        // mc = relu(exc - (inh @ Wl + bl))
        mc_kernel<<<grid_mc, blk>>>(g_excinh_p, Wl + (size_t)l * NMC * HW * HW,
                                    bl + (size_t)l * NMC * HW, g_mc_p);
        // lateral = mc @ Wlat + blat
        sgemm_kernel<0><<<grid_sq, blk>>>(g_mc_p, Wlat + (size_t)l * DD, blat + (size_t)l * DIM,
                                          g_lat_p, DIM);
        // tmp = lateral @ Wv + bv   (reuse g_mc)
        sgemm_kernel<0><<<grid_sq, blk>>>(g_lat_p, Wv + (size_t)l * DD, bv + (size_t)l * DIM,
                                          g_mc_p, DIM);
        // attended = tmp @ Wo + bo  -> out[l]
        sgemm_kernel<0><<<grid_sq, blk>>>(g_mc_p, Wo + (size_t)l * DD, bo + (size_t)l * DIM,
                                          out + (size_t)l * BD, DIM);
    }

    // feedback: out[idx] += out[idx+1] @ fbW[i] + fbb[i], idx = 4..0
    for (int i = 0; i < NLAY - 1; i++) {
        int idx = NLAY - 2 - i;
        sgemm_kernel<2><<<grid_sq, blk>>>(out + (size_t)(idx + 1) * BD, fbW + (size_t)i * DD,
                                          fbb + (size_t)i * DIM, out + (size_t)idx * BD, DIM);
    }
}

// round 3
// speedup vs baseline: 2.3030x; 2.3030x over previous
#include <cuda_runtime.h>
#include <cuda_bf16.h>
#include <cstdint>

#define BATCH 16384
#define DIM   1024
#define NLAY  6
#define NMC   64
#define HW    16

#define BM 128
#define BN 128
#define BK 32
#define AST 40    // A smem row stride (bf16 elems), padded vs 32
#define WST 136   // W smem row stride (bf16 elems), padded vs 128

// ---------------- scratch (static device globals; no cudaMalloc allowed) ----------------
__device__ float g_Wei[NLAY * DIM * 2 * DIM];       // fused [l][k][n] (48MB)
__device__ float g_bei[NLAY * 2 * DIM];
__device__ float g_excinh[(size_t)BATCH * 2 * DIM]; // [B, 2048] exc|inh (128MB)
__device__ float g_mc[(size_t)BATCH * DIM];
__device__ float g_lat[(size_t)BATCH * DIM];

// ---------------- weight / bias repack ----------------
__global__ void pack_wei_kernel(const float* __restrict__ We, const float* __restrict__ Wi) {
    size_t i = (size_t)blockIdx.x * blockDim.x + threadIdx.x;
    const size_t total = (size_t)NLAY * DIM * 2 * DIM;
    if (i >= total) return;
    int l = (int)(i / ((size_t)DIM * 2 * DIM));
    size_t r = i % ((size_t)DIM * 2 * DIM);
    int k = (int)(r / (2 * DIM));
    int n = (int)(r % (2 * DIM));
    const float* src;
    int nn;
    if (n < DIM) { src = We; nn = n; } else { src = Wi; nn = n - DIM; }
    int m = nn / HW, h = nn % HW;
    g_Wei[i] = src[(((size_t)l * NMC + m) * DIM + k) * HW + h];
}

__global__ void pack_bias_kernel(const float* __restrict__ be, const float* __restrict__ bi) {
    int i = blockIdx.x * blockDim.x + threadIdx.x;
    if (i >= NLAY * 2 * DIM) return;
    int l = i / (2 * DIM);
    int n = i % (2 * DIM);
    g_bei[i] = (n < DIM) ? be[l * DIM + n] : bi[l * DIM + (n - DIM)];
}

// ---------------- bf16 split helpers ----------------
__device__ __forceinline__ uint32_t cvt_bf16x2(float lo_elem, float hi_elem) {
    uint32_t r;
    asm("cvt.rn.bf16x2.f32 %0, %1, %2;" : "=r"(r) : "f"(hi_elem), "f"(lo_elem));
    return r;
}

// split float4 (4 consecutive elems) into hi pair-regs and lo pair-regs
__device__ __forceinline__ void split4(float4 v, uint32_t& h0, uint32_t& h1,
                                       uint32_t& l0, uint32_t& l1) {
    h0 = cvt_bf16x2(v.x, v.y);
    h1 = cvt_bf16x2(v.z, v.w);
    float hx = __uint_as_float(h0 << 16);
    float hy = __uint_as_float(h0 & 0xffff0000u);
    float hz = __uint_as_float(h1 << 16);
    float hw = __uint_as_float(h1 & 0xffff0000u);
    l0 = cvt_bf16x2(v.x - hx, v.y - hy);
    l1 = cvt_bf16x2(v.z - hz, v.w - hw);
}

__device__ __forceinline__ void ldsm4(uint32_t addr, uint32_t& r0, uint32_t& r1,
                                      uint32_t& r2, uint32_t& r3) {
    asm volatile("ldmatrix.sync.aligned.m8n8.x4.shared.b16 {%0,%1,%2,%3}, [%4];"
                 : "=r"(r0), "=r"(r1), "=r"(r2), "=r"(r3) : "r"(addr));
}
__device__ __forceinline__ void ldsm4t(uint32_t addr, uint32_t& r0, uint32_t& r1,
                                       uint32_t& r2, uint32_t& r3) {
    asm volatile("ldmatrix.sync.aligned.m8n8.x4.trans.shared.b16 {%0,%1,%2,%3}, [%4];"
                 : "=r"(r0), "=r"(r1), "=r"(r2), "=r"(r3) : "r"(addr));
}

__device__ __forceinline__ void mma16816(float* c, const uint32_t* a, const uint32_t* b) {
    asm volatile(
        "mma.sync.aligned.m16n8k16.row.col.f32.bf16.bf16.f32 "
        "{%0,%1,%2,%3}, {%4,%5,%6,%7}, {%8,%9}, {%0,%1,%2,%3};"
        : "+f"(c[0]), "+f"(c[1]), "+f"(c[2]), "+f"(c[3])
        : "r"(a[0]), "r"(a[1]), "r"(a[2]), "r"(a[3]), "r"(b[0]), "r"(b[1]));
}

// ---------------- bf16x3 compensated GEMM: C = epi(A[M,K=1024] @ W[K,N] + bias) ----------------
// EPI 0: bias     EPI 1: bias + relu     EPI 2: C += A@W + bias
template <int EPI>
__global__ __launch_bounds__(256, 1)
void bgemm_kernel(const float* __restrict__ A, const float* __restrict__ W,
                  const float* __restrict__ bias, float* __restrict__ C, int N) {
    const int K = DIM;
    extern __shared__ char smem_raw[];
    __nv_bfloat16* sAh = (__nv_bfloat16*)smem_raw;        // [2][BM][AST]
    __nv_bfloat16* sAl = sAh + 2 * BM * AST;
    __nv_bfloat16* sWh = sAl + 2 * BM * AST;              // [2][BK][WST]
    __nv_bfloat16* sWl = sWh + 2 * BK * WST;

    const uint32_t sAh_u = (uint32_t)__cvta_generic_to_shared(sAh);
    const uint32_t sAl_u = (uint32_t)__cvta_generic_to_shared(sAl);
    const uint32_t sWh_u = (uint32_t)__cvta_generic_to_shared(sWh);
    const uint32_t sWl_u = (uint32_t)__cvta_generic_to_shared(sWl);

    const int tid = threadIdx.x;
    const int lane = tid & 31, wid = tid >> 5;
    const int wm = wid >> 2, wn = wid & 3;          // warp grid 2 (M) x 4 (N)
    const int bx = blockIdx.x, by = blockIdx.y;

    const float* Ab = A + (size_t)by * BM * K;
    const float* Wb = W + (size_t)bx * BN;

    // global loader mapping (per i = 0..3, 128B-coalesced)
    const int ar = tid >> 3, ac = (tid & 7) * 4;    // A: row i*32+ar, col ac
    const int wr = tid >> 5, wc = (tid & 31) * 4;   // W: row i*8+wr,  col wc

    float acc[4][4][4];
#pragma unroll
    for (int mt = 0; mt < 4; mt++)
#pragma unroll
        for (int nt = 0; nt < 4; nt++)
#pragma unroll
            for (int q = 0; q < 4; q++) acc[mt][nt][q] = 0.f;

    float4 pa[4], pw[4];

    // prologue: tile 0
#pragma unroll
    for (int i = 0; i < 4; i++)
        pa[i] = *(const float4*)(Ab + (size_t)(i * 32 + ar) * K + ac);
#pragma unroll
    for (int i = 0; i < 4; i++)
        pw[i] = *(const float4*)(Wb + (size_t)(i * 8 + wr) * N + wc);
    {
#pragma unroll
        for (int i = 0; i < 4; i++) {
            uint32_t h0, h1, l0, l1;
            split4(pa[i], h0, h1, l0, l1);
            int off = (i * 32 + ar) * AST + ac;
            *(uint2*)(sAh + off) = make_uint2(h0, h1);
            *(uint2*)(sAl + off) = make_uint2(l0, l1);
        }
#pragma unroll
        for (int i = 0; i < 4; i++) {
            uint32_t h0, h1, l0, l1;
            split4(pw[i], h0, h1, l0, l1);
            int off = (i * 8 + wr) * WST + wc;
            *(uint2*)(sWh + off) = make_uint2(h0, h1);
            *(uint2*)(sWl + off) = make_uint2(l0, l1);
        }
    }
    __syncthreads();

    const int arow = lane & 15;
    const int acol8 = (lane >> 4) * 8;

    const int NT = K / BK;   // 32
    for (int t = 0; t < NT; t++) {
        const int cur = t & 1;
        if (t + 1 < NT) {
            const int ko = (t + 1) * BK;
#pragma unroll
            for (int i = 0; i < 4; i++)
                pa[i] = *(const float4*)(Ab + (size_t)(i * 32 + ar) * K + ko + ac);
#pragma unroll
            for (int i = 0; i < 4; i++)
                pw[i] = *(const float4*)(Wb + (size_t)(ko + i * 8 + wr) * N + wc);
        }

#pragma unroll
        for (int ks = 0; ks < 2; ks++) {
            uint32_t ah[4][4], al[4][4], bh[4][2], bl[4][2];
#pragma unroll
            for (int mt = 0; mt < 4; mt++) {
                uint32_t off = (uint32_t)((cur * BM + wm * 64 + mt * 16 + arow) * AST +
                                          ks * 16 + acol8) * 2;
                ldsm4(sAh_u + off, ah[mt][0], ah[mt][1], ah[mt][2], ah[mt][3]);
                ldsm4(sAl_u + off, al[mt][0], al[mt][1], al[mt][2], al[mt][3]);
            }
#pragma unroll
            for (int np = 0; np < 2; np++) {
                uint32_t off = (uint32_t)((cur * BK + ks * 16 + arow) * WST +
                                          wn * 32 + np * 16 + acol8) * 2;
                uint32_t r0, r1, r2, r3;
                ldsm4t(sWh_u + off, r0, r1, r2, r3);
                bh[np * 2][0] = r0; bh[np * 2][1] = r1;
                bh[np * 2 + 1][0] = r2; bh[np * 2 + 1][1] = r3;
                ldsm4t(sWl_u + off, r0, r1, r2, r3);
                bl[np * 2][0] = r0; bl[np * 2][1] = r1;
                bl[np * 2 + 1][0] = r2; bl[np * 2 + 1][1] = r3;
            }
            // term 1: Ah @ Wh
#pragma unroll
            for (int mt = 0; mt < 4; mt++)
#pragma unroll
                for (int nt = 0; nt < 4; nt++) mma16816(acc[mt][nt], ah[mt], bh[nt]);
            // term 2: Ah @ Wl
#pragma unroll
            for (int mt = 0; mt < 4; mt++)
#pragma unroll
                for (int nt = 0; nt < 4; nt++) mma16816(acc[mt][nt], ah[mt], bl[nt]);
            // term 3: Al @ Wh
#pragma unroll
            for (int mt = 0; mt < 4; mt++)
#pragma unroll
                for (int nt = 0; nt < 4; nt++) mma16816(acc[mt][nt], al[mt], bh[nt]);
        }

        if (t + 1 < NT) {
            const int nxt = cur ^ 1;
#pragma unroll
            for (int i = 0; i < 4; i++) {
                uint32_t h0, h1, l0, l1;
                split4(pa[i], h0, h1, l0, l1);
                int off = (nxt * BM + i * 32 + ar) * AST + ac;
                *(uint2*)(sAh + off) = make_uint2(h0, h1);
                *(uint2*)(sAl + off) = make_uint2(l0, l1);
            }
#pragma unroll
            for (int i = 0; i < 4; i++) {
                uint32_t h0, h1, l0, l1;
                split4(pw[i], h0, h1, l0, l1);
                int off = (nxt * BK + i * 8 + wr) * WST + wc;
                *(uint2*)(sWh + off) = make_uint2(h0, h1);
                *(uint2*)(sWl + off) = make_uint2(l0, l1);
            }
            __syncthreads();
        }
    }

    // epilogue
    const int g = lane >> 2;
    const int tg = lane & 3;
#pragma unroll
    for (int mt = 0; mt < 4; mt++) {
        const int r0 = by * BM + wm * 64 + mt * 16 + g;
#pragma unroll
        for (int nt = 0; nt < 4; nt++) {
            const int col = bx * BN + wn * 32 + nt * 8 + tg * 2;
            float2 bv = *(const float2*)(bias + col);
            float2 v0, v1;
            v0.x = acc[mt][nt][0] + bv.x;  v0.y = acc[mt][nt][1] + bv.y;
            v1.x = acc[mt][nt][2] + bv.x;  v1.y = acc[mt][nt][3] + bv.y;
            float* p0 = C + (size_t)r0 * N + col;
            float* p1 = C + (size_t)(r0 + 8) * N + col;
            if (EPI == 1) {
                v0.x = fmaxf(v0.x, 0.f); v0.y = fmaxf(v0.y, 0.f);
                v1.x = fmaxf(v1.x, 0.f); v1.y = fmaxf(v1.y, 0.f);
            } else if (EPI == 2) {
                float2 o0 = *(const float2*)p0;
                float2 o1 = *(const float2*)p1;
                v0.x += o0.x; v0.y += o0.y; v1.x += o1.x; v1.y += o1.y;
            }
            *(float2*)p0 = v0;
            *(float2*)p1 = v1;
        }
    }
}

// ---------------- minicolumn block-diag: mc = relu(exc - (inh @ Wl[m] + bl[m])) ----------------
__global__ __launch_bounds__(256)
void mc_kernel(const float* __restrict__ excinh, const float* __restrict__ Wl,
               const float* __restrict__ bl, float* __restrict__ mc) {
    __shared__ float sW[HW * HW];
    __shared__ float sb[HW];
    const int m = blockIdx.y;
    if (threadIdx.x < HW * HW) sW[threadIdx.x] = Wl[m * HW * HW + threadIdx.x];
    if (threadIdx.x < HW)      sb[threadIdx.x] = bl[m * HW + threadIdx.x];
    __syncthreads();

    const int b = blockIdx.x * 256 + threadIdx.x;
    const float* row = excinh + (size_t)b * (2 * DIM);

    float inh[HW], exc[HW];
#pragma unroll
    for (int j = 0; j < 4; j++) {
        float4 vi = *(const float4*)(row + DIM + m * HW + j * 4);
        inh[j * 4 + 0] = vi.x; inh[j * 4 + 1] = vi.y; inh[j * 4 + 2] = vi.z; inh[j * 4 + 3] = vi.w;
        float4 ve = *(const float4*)(row + m * HW + j * 4);
        exc[j * 4 + 0] = ve.x; exc[j * 4 + 1] = ve.y; exc[j * 4 + 2] = ve.z; exc[j * 4 + 3] = ve.w;
    }

    float out[HW];
#pragma unroll
    for (int k = 0; k < HW; k++) {
        float lat = sb[k];
#pragma unroll
        for (int h = 0; h < HW; h++) lat += inh[h] * sW[h * HW + k];
        out[k] = fmaxf(exc[k] - lat, 0.f);
    }

    float* dst = mc + (size_t)b * DIM + m * HW;
#pragma unroll
    for (int j = 0; j < 4; j++) {
        float4 v;
        v.x = out[j * 4 + 0]; v.y = out[j * 4 + 1]; v.z = out[j * 4 + 2]; v.w = out[j * 4 + 3];
        *(float4*)(dst + j * 4) = v;
    }
}

// ---------------- driver ----------------
extern "C" void kernel_launch(void* const* d_in, const int* in_sizes, int n_in,
                              void* d_out, int out_size) {
    const float* x    = (const float*)d_in[0];
    const float* We   = (const float*)d_in[1];
    const float* be   = (const float*)d_in[2];
    const float* Wi   = (const float*)d_in[3];
    const float* bi   = (const float*)d_in[4];
    const float* Wl   = (const float*)d_in[5];
    const float* bl   = (const float*)d_in[6];
    const float* Wlat = (const float*)d_in[7];
    const float* blat = (const float*)d_in[8];
    const float* Wv   = (const float*)d_in[9];
    const float* bv   = (const float*)d_in[10];
    const float* Wo   = (const float*)d_in[11];
    const float* bo   = (const float*)d_in[12];
    const float* fbW  = (const float*)d_in[13];
    const float* fbb  = (const float*)d_in[14];
    float* out = (float*)d_out;

    const size_t BD = (size_t)BATCH * DIM;
    const size_t DD = (size_t)DIM * DIM;

    float* g_Wei_p;     cudaGetSymbolAddress((void**)&g_Wei_p, g_Wei);
    float* g_bei_p;     cudaGetSymbolAddress((void**)&g_bei_p, g_bei);
    float* g_excinh_p;  cudaGetSymbolAddress((void**)&g_excinh_p, g_excinh);
    float* g_mc_p;      cudaGetSymbolAddress((void**)&g_mc_p, g_mc);
    float* g_lat_p;     cudaGetSymbolAddress((void**)&g_lat_p, g_lat);

    const int SMEM_BYTES = (2 * BM * AST * 2 + 2 * BK * WST * 2) * 2;  // 75776
    cudaFuncSetAttribute(bgemm_kernel<0>, cudaFuncAttributeMaxDynamicSharedMemorySize, SMEM_BYTES);
    cudaFuncSetAttribute(bgemm_kernel<1>, cudaFuncAttributeMaxDynamicSharedMemorySize, SMEM_BYTES);
    cudaFuncSetAttribute(bgemm_kernel<2>, cudaFuncAttributeMaxDynamicSharedMemorySize, SMEM_BYTES);

    // repack fused We|Wi weights + biases
    {
        size_t total = (size_t)NLAY * DIM * 2 * DIM;
        pack_wei_kernel<<<(unsigned)((total + 255) / 256), 256>>>(We, Wi);
        pack_bias_kernel<<<(NLAY * 2 * DIM + 255) / 256, 256>>>(be, bi);
    }

    dim3 blk(256);
    dim3 grid_wide(2 * DIM / BN, BATCH / BM);  // N = 2048
    dim3 grid_sq(DIM / BN, BATCH / BM);        // N = 1024
    dim3 grid_mc(BATCH / 256, NMC);

    for (int l = 0; l < NLAY; l++) {
        const float* xin = (l == 0) ? x : (out + (size_t)(l - 1) * BD);
        bgemm_kernel<1><<<grid_wide, blk, SMEM_BYTES>>>(xin, g_Wei_p + (size_t)l * DIM * 2 * DIM,
                                                        g_bei_p + (size_t)l * 2 * DIM, g_excinh_p, 2 * DIM);
        mc_kernel<<<grid_mc, blk>>>(g_excinh_p, Wl + (size_t)l * NMC * HW * HW,
                                    bl + (size_t)l * NMC * HW, g_mc_p);
        bgemm_kernel<0><<<grid_sq, blk, SMEM_BYTES>>>(g_mc_p, Wlat + (size_t)l * DD, blat + (size_t)l * DIM,
                                                      g_lat_p, DIM);
        bgemm_kernel<0><<<grid_sq, blk, SMEM_BYTES>>>(g_lat_p, Wv + (size_t)l * DD, bv + (size_t)l * DIM,
                                                      g_mc_p, DIM);
        bgemm_kernel<0><<<grid_sq, blk, SMEM_BYTES>>>(g_mc_p, Wo + (size_t)l * DD, bo + (size_t)l * DIM,
                                                      out + (size_t)l * BD, DIM);
    }

    for (int i = 0; i < NLAY - 1; i++) {
        int idx = NLAY - 2 - i;
        bgemm_kernel<2><<<grid_sq, blk, SMEM_BYTES>>>(out + (size_t)(idx + 1) * BD, fbW + (size_t)i * DD,
                                                      fbb + (size_t)i * DIM, out + (size_t)idx * BD, DIM);
    }
}